// round 16
// baseline (speedup 1.0000x reference)
#include <cuda_runtime.h>
#include <cuda_fp16.h>
#include <cstdint>

#define B_   2
#define L_   2048
#define DIM_ 3072
#define H_   24
#define HD_  128
#define TOK  (B_ * L_)          // 4096
#define N_QKV (3 * DIM_)        // 9216

// ---------------- scratch (device globals — no allocation allowed) ----------
__device__ __half g_qh[(size_t)B_ * H_ * L_ * HD_];  // post rms+rope, q pre-scaled
__device__ __half g_kh[(size_t)B_ * H_ * L_ * HD_];
__device__ __half g_vh[(size_t)B_ * H_ * L_ * HD_];
__device__ __half g_xh[(size_t)TOK * DIM_];
__device__ __half g_wqh[(size_t)N_QKV * DIM_];
__device__ __half g_wph[(size_t)DIM_ * DIM_];
__device__ __half g_oh[(size_t)TOK * DIM_];

// ============================================================================
// helpers
// ============================================================================
__device__ __forceinline__ void mma_f16(float* d, const uint32_t* a,
                                        uint32_t b0, uint32_t b1) {
    asm volatile(
        "mma.sync.aligned.m16n8k16.row.col.f32.f16.f16.f32 "
        "{%0,%1,%2,%3}, {%4,%5,%6,%7}, {%8,%9}, {%0,%1,%2,%3};"
        : "+f"(d[0]), "+f"(d[1]), "+f"(d[2]), "+f"(d[3])
        : "r"(a[0]), "r"(a[1]), "r"(a[2]), "r"(a[3]), "r"(b0), "r"(b1));
}
__device__ __forceinline__ uint32_t smem_u32(const void* p) {
    uint32_t a;
    asm("{ .reg .u64 t; cvta.to.shared.u64 t, %1; cvt.u32.u64 %0, t; }"
        : "=r"(a) : "l"(p));
    return a;
}
__device__ __forceinline__ void ldsm4(uint32_t* d, uint32_t saddr) {
    asm volatile("ldmatrix.sync.aligned.m8n8.x4.shared.b16 {%0,%1,%2,%3}, [%4];"
        : "=r"(d[0]), "=r"(d[1]), "=r"(d[2]), "=r"(d[3]) : "r"(saddr));
}
__device__ __forceinline__ void ldsm4t(uint32_t* d, uint32_t saddr) {
    asm volatile("ldmatrix.sync.aligned.m8n8.x4.trans.shared.b16 {%0,%1,%2,%3}, [%4];"
        : "=r"(d[0]), "=r"(d[1]), "=r"(d[2]), "=r"(d[3]) : "r"(saddr));
}
__device__ __forceinline__ void cpa16(uint32_t s, const void* g) {
    asm volatile("cp.async.cg.shared.global [%0], [%1], 16;"
                 :: "r"(s), "l"(g) : "memory");
}
#define CP_COMMIT() asm volatile("cp.async.commit_group;" ::: "memory")
#define CP_WAIT0()  asm volatile("cp.async.wait_group 0;" ::: "memory")
#define CP_WAIT1()  asm volatile("cp.async.wait_group 1;" ::: "memory")
#define CP_WAIT2()  asm volatile("cp.async.wait_group 2;" ::: "memory")

// ============================================================================
// convert fp32 -> fp16 (RN)
// ============================================================================
__global__ __launch_bounds__(256) void to_fp16(
    const float4* __restrict__ in, __half* __restrict__ out, int n4)
{
    int i = blockIdx.x * 256 + threadIdx.x;
    if (i < n4) {
        float4 v = in[i];
        __half2* o = reinterpret_cast<__half2*>(out + (size_t)i * 4);
        o[0] = __floats2half2_rn(v.x, v.y);
        o[1] = __floats2half2_rn(v.z, v.w);
    }
}

// ============================================================================
// fp16 mma.sync GEMM, cp.async 4-stage, 2 CTAs/SM.
// MODE 0: C = A@W^T + bias -> Cout (fp32 row-major).
// MODE 1: QKV + FUSED RMSNorm+RoPE epilogue.
//   A BN=128 tile == one head of one segment (q/k/v). For q,k: add bias,
//   row-wise rms (shfl over c4 quad + 2KB smem across 4 n-warps), scale,
//   rope (thread's (even,odd) col pairs == rope 2x2 blocks), write fp16
//   g_qh (pre-scaled 1/sqrt(128)) / g_kh. v: bias + fp16 -> g_vh.
// ============================================================================
#define HSTR 40
#define AT_HALVES (128 * HSTR)
#define STG_B (2 * AT_HALVES * 2)
#define GEMM_SMEM (4 * STG_B)               // 81920 B

template <int MODE>
__global__ __launch_bounds__(256, 2) void gemm_h(
    const __half* __restrict__ A, const __half* __restrict__ W,
    const float* __restrict__ bias, float* __restrict__ Cout,
    const float* __restrict__ pe,
    const float* __restrict__ q_scale, const float* __restrict__ k_scale,
    int M, int N, int K)
{
    extern __shared__ __half hsm[];

    const int tid = threadIdx.x;
    const int wid = tid >> 5, lane = tid & 31;
    const int wm = wid >> 2, wn = wid & 3;
    const int qr = lane >> 2, c4 = lane & 3;
    const int row0 = blockIdx.y * 128;
    const int col0 = blockIdx.x * 128;
    const int NSTG = K / 32;

    const int crow = tid >> 2;
    const int cc8  = (tid & 3) * 8;

    const int lmr = (lane & 7) + (lane & 8);
    const uint32_t lmoff = (uint32_t)(lmr * HSTR + ((lane >> 4) << 3)) * 2;
    const uint32_t sBase = smem_u32(hsm);

    const __half* ga = A + (size_t)(row0 + crow) * K + cc8;
    const __half* gb = W + (size_t)(col0 + crow) * K + cc8;
    const uint32_t dOff = (uint32_t)(crow * HSTR + cc8) * 2;
    const uint32_t dRow64 = (uint32_t)(64 * HSTR) * 2;

    float acc[4][4][4];
#pragma unroll
    for (int mm = 0; mm < 4; mm++)
#pragma unroll
        for (int nn = 0; nn < 4; nn++)
#pragma unroll
            for (int q = 0; q < 4; q++) acc[mm][nn][q] = 0.f;

    auto issue_stage = [&](int st, int kt) {
        uint32_t s0 = sBase + st * STG_B + dOff;
        cpa16(s0, ga + kt);
        cpa16(s0 + dRow64, ga + (size_t)64 * K + kt);
        uint32_t s1 = s0 + AT_HALVES * 2;
        cpa16(s1, gb + kt);
        cpa16(s1 + dRow64, gb + (size_t)64 * K + kt);
    };

#pragma unroll
    for (int st = 0; st < 3; st++) { issue_stage(st, st * 32); CP_COMMIT(); }

    for (int s = 0; s < NSTG; ++s) {
        CP_WAIT2();
        __syncthreads();

        if (s + 3 < NSTG) issue_stage((s + 3) & 3, (s + 3) * 32);
        CP_COMMIT();

        const uint32_t sA = sBase + (uint32_t)((s & 3) * STG_B);
        const uint32_t sB = sA + AT_HALVES * 2;

#pragma unroll
        for (int ki = 0; ki < 2; ki++) {
            const uint32_t ko = (uint32_t)(ki * 16) * 2;
            uint32_t a[4][4], bb[2][4];
#pragma unroll
            for (int mm = 0; mm < 4; mm++)
                ldsm4(a[mm], sA + (uint32_t)((wm * 64 + mm * 16) * HSTR * 2)
                               + ko + lmoff);
#pragma unroll
            for (int np = 0; np < 2; np++)
                ldsm4(bb[np], sB + (uint32_t)((wn * 32 + np * 16) * HSTR * 2)
                                + ko + lmoff);
#pragma unroll
            for (int np = 0; np < 2; np++)
#pragma unroll
                for (int mm = 0; mm < 4; mm++) {
                    mma_f16(acc[mm][2 * np],     a[mm], bb[np][0], bb[np][2]);
                    mma_f16(acc[mm][2 * np + 1], a[mm], bb[np][1], bb[np][3]);
                }
        }
    }

    // ---- add bias in place ----
#pragma unroll
    for (int nn = 0; nn < 4; nn++) {
        const int n = col0 + wn * 32 + nn * 8 + c4 * 2;
        const float b0 = bias[n], b1 = bias[n + 1];
#pragma unroll
        for (int mm = 0; mm < 4; mm++) {
#pragma unroll
            for (int half = 0; half < 2; half++) {
                acc[mm][nn][half * 2]     += b0;
                acc[mm][nn][half * 2 + 1] += b1;
            }
        }
    }

    if (MODE == 0) {
#pragma unroll
        for (int nn = 0; nn < 4; nn++) {
            const int n = col0 + wn * 32 + nn * 8 + c4 * 2;
#pragma unroll
            for (int mm = 0; mm < 4; mm++) {
#pragma unroll
                for (int half = 0; half < 2; half++) {
                    const int m = row0 + wm * 64 + mm * 16 + half * 8 + qr;
                    *reinterpret_cast<float2*>(&Cout[(size_t)m * N + n]) =
                        make_float2(acc[mm][nn][half * 2], acc[mm][nn][half * 2 + 1]);
                }
            }
        }
    } else {
        const int sseg = col0 / DIM_;
        const int rem  = col0 - sseg * DIM_;
        const int hh   = rem >> 7;

        if (sseg == 2) {
            // ---- v: straight fp16 scatter ----
#pragma unroll
            for (int nn = 0; nn < 4; nn++) {
                const int d = wn * 32 + nn * 8 + c4 * 2;
#pragma unroll
                for (int mm = 0; mm < 4; mm++) {
#pragma unroll
                    for (int half = 0; half < 2; half++) {
                        const int m = row0 + wm * 64 + mm * 16 + half * 8 + qr;
                        const int l = m & (L_ - 1), bb = m >> 11;
                        size_t idx = ((size_t)(bb * H_ + hh) * L_ + l) * HD_ + d;
                        *reinterpret_cast<__half2*>(&g_vh[idx]) =
                            __floats2half2_rn(acc[mm][nn][half * 2],
                                              acc[mm][nn][half * 2 + 1]);
                    }
                }
            }
        } else {
            // ---- q/k: fused RMSNorm + RoPE ----
            __syncthreads();                       // stage smem now dead
            float* ssred = reinterpret_cast<float*>(hsm);   // [128][4]
            const float* scale = (sseg == 0) ? q_scale : k_scale;
            const float post = (sseg == 0) ? 0.08838834764831845f : 1.0f;

            // per-row partial sum over this warp's 32 cols
#pragma unroll
            for (int mm = 0; mm < 4; mm++) {
#pragma unroll
                for (int half = 0; half < 2; half++) {
                    float ss = 0.f;
#pragma unroll
                    for (int nn = 0; nn < 4; nn++) {
                        float a0 = acc[mm][nn][half * 2];
                        float a1 = acc[mm][nn][half * 2 + 1];
                        ss += a0 * a0 + a1 * a1;
                    }
                    ss += __shfl_xor_sync(~0u, ss, 1);
                    ss += __shfl_xor_sync(~0u, ss, 2);
                    if (c4 == 0)
                        ssred[(wm * 64 + mm * 16 + half * 8 + qr) * 4 + wn] = ss;
                }
            }
            __syncthreads();

#pragma unroll
            for (int mm = 0; mm < 4; mm++) {
#pragma unroll
                for (int half = 0; half < 2; half++) {
                    const int rl = wm * 64 + mm * 16 + half * 8 + qr;
                    float s4 = ssred[rl * 4 + 0] + ssred[rl * 4 + 1]
                             + ssred[rl * 4 + 2] + ssred[rl * 4 + 3];
                    float rr = rsqrtf(s4 * (1.0f / 128.0f) + 1e-6f);

                    const int m = row0 + rl;
                    const int l = m & (L_ - 1), bb = m >> 11;
                    const float* pe_l = pe + (size_t)l * 256;
                    __half* dst = ((sseg == 0) ? g_qh : g_kh)
                                  + ((size_t)(bb * H_ + hh) * L_ + l) * HD_;
#pragma unroll
                    for (int nn = 0; nn < 4; nn++) {
                        const int d = wn * 32 + nn * 8 + c4 * 2;
                        float2 sc = *reinterpret_cast<const float2*>(&scale[d]);
                        float n0 = acc[mm][nn][half * 2]     * rr * sc.x;
                        float n1 = acc[mm][nn][half * 2 + 1] * rr * sc.y;
                        float4 rm = *reinterpret_cast<const float4*>(&pe_l[(d >> 1) * 4]);
                        float o0 = (rm.x * n0 + rm.y * n1) * post;
                        float o1 = (rm.z * n0 + rm.w * n1) * post;
                        *reinterpret_cast<__half2*>(&dst[d]) = __floats2half2_rn(o0, o1);
                    }
                }
            }
        }
    }
}

// ============================================================================
// Flash attention, fp16 m16n8k16, cp.async double-buffered K/V (round 15)
// ============================================================================
#define QH_STR 136
#define PH_STR 72
#define Q_BYTES   (128 * QH_STR * 2)         // 34816
#define KMAT_B    (64 * QH_STR * 2)          // 17408
#define KV_STG    (2 * KMAT_B)               // 34816
#define ATTN_SMEM (Q_BYTES + 2 * KV_STG)     // 104448

__global__ __launch_bounds__(256, 1) void attn_h()
{
    extern __shared__ __half hs[];
    const uint32_t sQ  = smem_u32(hs);
    const uint32_t sKV = sQ + Q_BYTES;

    const int tid = threadIdx.x, w = tid >> 5, lane = tid & 31;
    const int qr = lane >> 2, c4 = lane & 3;
    const int q0 = blockIdx.x * 128;
    const int h = blockIdx.y, b = blockIdx.z;

    const size_t hoff = (size_t)(b * H_ + h) * L_ * HD_;
    const __half* qg = g_qh + hoff + (size_t)q0 * HD_;
    const __half* kg = g_kh + hoff;
    const __half* vg = g_vh + hoff;

    const int lmr = (lane & 7) + (lane & 8);
    const int lc8 = (lane >> 4) << 3;

    {
        int qrow = tid >> 1, qc = (tid & 1) * 64;
#pragma unroll
        for (int j = 0; j < 8; j++)
            cpa16(sQ + (uint32_t)(qrow * QH_STR + qc + j * 8) * 2,
                  qg + (size_t)qrow * HD_ + qc + j * 8);
        CP_COMMIT();
    }
    const int crow = tid >> 2;
    const int cb   = (tid & 3) * 32;
    auto issue_kv = [&](int st, int kt) {
        uint32_t kd = sKV + st * KV_STG + (uint32_t)(crow * QH_STR + cb) * 2;
        const __half* ks = kg + (size_t)(kt + crow) * HD_ + cb;
        const __half* vs = vg + (size_t)(kt + crow) * HD_ + cb;
#pragma unroll
        for (int j = 0; j < 4; j++) {
            cpa16(kd + j * 16, ks + j * 8);
            cpa16(kd + KMAT_B + j * 16, vs + j * 8);
        }
    };
    issue_kv(0, 0);
    CP_COMMIT();

    CP_WAIT1();
    __syncthreads();

    uint32_t qf[8][4];
    {
        uint32_t qbase = sQ + (uint32_t)((w * 16 + lmr) * QH_STR + lc8) * 2;
#pragma unroll
        for (int ks = 0; ks < 8; ks++)
            ldsm4(qf[ks], qbase + ks * 32);
    }

    float of[16][4];
#pragma unroll
    for (int nt = 0; nt < 16; nt++)
#pragma unroll
        for (int q = 0; q < 4; q++) of[nt][q] = 0.f;
    float m0 = -1e30f, m1 = -1e30f, l0 = 0.f, l1 = 0.f;

    for (int t = 0; t < L_ / 64; t++) {
        CP_WAIT0();
        __syncthreads();
        if (t + 1 < L_ / 64) issue_kv((t + 1) & 1, (t + 1) * 64);
        CP_COMMIT();

        const uint32_t sK = sKV + (t & 1) * KV_STG;
        const uint32_t sV = sK + KMAT_B;

        float sacc[8][4];
#pragma unroll
        for (int nn = 0; nn < 8; nn++)
#pragma unroll
            for (int q = 0; q < 4; q++) sacc[nn][q] = 0.f;

#pragma unroll
        for (int ks = 0; ks < 8; ks++) {
            uint32_t kb[4][4];
#pragma unroll
            for (int np = 0; np < 4; np++)
                ldsm4(kb[np], sK + (uint32_t)((np * 16 + lmr) * QH_STR + lc8) * 2
                                + ks * 32);
#pragma unroll
            for (int np = 0; np < 4; np++) {
                mma_f16(sacc[2 * np],     qf[ks], kb[np][0], kb[np][2]);
                mma_f16(sacc[2 * np + 1], qf[ks], kb[np][1], kb[np][3]);
            }
        }

        float mx0 = -1e30f, mx1 = -1e30f;
#pragma unroll
        for (int nn = 0; nn < 8; nn++) {
            mx0 = fmaxf(mx0, fmaxf(sacc[nn][0], sacc[nn][1]));
            mx1 = fmaxf(mx1, fmaxf(sacc[nn][2], sacc[nn][3]));
        }
        mx0 = fmaxf(mx0, __shfl_xor_sync(~0u, mx0, 1));
        mx0 = fmaxf(mx0, __shfl_xor_sync(~0u, mx0, 2));
        mx1 = fmaxf(mx1, __shfl_xor_sync(~0u, mx1, 1));
        mx1 = fmaxf(mx1, __shfl_xor_sync(~0u, mx1, 2));

        float nm0 = fmaxf(m0, mx0), nm1 = fmaxf(m1, mx1);
        float a0 = __expf(m0 - nm0), a1 = __expf(m1 - nm1);
        m0 = nm0; m1 = nm1;

        float s0 = 0.f, s1 = 0.f;
#pragma unroll
        for (int nn = 0; nn < 8; nn++) {
            sacc[nn][0] = __expf(sacc[nn][0] - nm0); s0 += sacc[nn][0];
            sacc[nn][1] = __expf(sacc[nn][1] - nm0); s0 += sacc[nn][1];
            sacc[nn][2] = __expf(sacc[nn][2] - nm1); s1 += sacc[nn][2];
            sacc[nn][3] = __expf(sacc[nn][3] - nm1); s1 += sacc[nn][3];
        }
        s0 += __shfl_xor_sync(~0u, s0, 1); s0 += __shfl_xor_sync(~0u, s0, 2);
        s1 += __shfl_xor_sync(~0u, s1, 1); s1 += __shfl_xor_sync(~0u, s1, 2);
        l0 = l0 * a0 + s0; l1 = l1 * a1 + s1;

#pragma unroll
        for (int nt = 0; nt < 16; nt++) {
            of[nt][0] *= a0; of[nt][1] *= a0;
            of[nt][2] *= a1; of[nt][3] *= a1;
        }

        {
            int r0 = w * 16 + qr;
#pragma unroll
            for (int nn = 0; nn < 8; nn++) {
                int col = nn * 8 + c4 * 2;
                *reinterpret_cast<__half2*>(hs + r0 * PH_STR + col) =
                    __floats2half2_rn(sacc[nn][0], sacc[nn][1]);
                *reinterpret_cast<__half2*>(hs + (r0 + 8) * PH_STR + col) =
                    __floats2half2_rn(sacc[nn][2], sacc[nn][3]);
            }
        }
        __syncwarp();

#pragma unroll
        for (int kv = 0; kv < 4; kv++) {
            uint32_t pf[4];
            ldsm4(pf, sQ + (uint32_t)((w * 16 + lmr) * PH_STR + kv * 16 + lc8) * 2);
#pragma unroll
            for (int nt2 = 0; nt2 < 8; nt2++) {
                uint32_t vb[4];
                ldsm4t(vb, sV + (uint32_t)((kv * 16 + lmr) * QH_STR + nt2 * 16 + lc8) * 2);
                mma_f16(of[2 * nt2],     pf, vb[0], vb[1]);
                mma_f16(of[2 * nt2 + 1], pf, vb[2], vb[3]);
            }
        }
    }

    {
        float inv0 = 1.0f / l0, inv1 = 1.0f / l1;
        int r0 = q0 + w * 16 + qr;
        __half* og0 = g_oh + ((size_t)(b * L_) + r0) * DIM_ + h * HD_;
        __half* og1 = og0 + (size_t)8 * DIM_;
#pragma unroll
        for (int nt = 0; nt < 16; nt++) {
            int d = nt * 8 + c4 * 2;
            *reinterpret_cast<__half2*>(&og0[d]) =
                __floats2half2_rn(of[nt][0] * inv0, of[nt][1] * inv0);
            *reinterpret_cast<__half2*>(&og1[d]) =
                __floats2half2_rn(of[nt][2] * inv1, of[nt][3] * inv1);
        }
    }
}

// ============================================================================
extern "C" void kernel_launch(void* const* d_in, const int* in_sizes, int n_in,
                              void* d_out, int out_size)
{
    const float* x       = (const float*)d_in[0];
    const float* pe      = (const float*)d_in[1];
    const float* Wqkv    = (const float*)d_in[2];
    const float* bqkv    = (const float*)d_in[3];
    const float* q_scale = (const float*)d_in[4];
    const float* k_scale = (const float*)d_in[5];
    const float* Wproj   = (const float*)d_in[6];
    const float* bproj   = (const float*)d_in[7];
    float* out = (float*)d_out;

    cudaFuncSetAttribute(gemm_h<1>, cudaFuncAttributeMaxDynamicSharedMemorySize, GEMM_SMEM);
    cudaFuncSetAttribute(gemm_h<0>, cudaFuncAttributeMaxDynamicSharedMemorySize, GEMM_SMEM);
    cudaFuncSetAttribute(attn_h, cudaFuncAttributeMaxDynamicSharedMemorySize, ATTN_SMEM);

    __half* xh = nullptr; __half* wqh = nullptr; __half* wph = nullptr; __half* oh = nullptr;
    cudaGetSymbolAddress((void**)&xh, g_xh);
    cudaGetSymbolAddress((void**)&wqh, g_wqh);
    cudaGetSymbolAddress((void**)&wph, g_wph);
    cudaGetSymbolAddress((void**)&oh, g_oh);

    // 0) convert x, Wqkv, Wproj to fp16 scratch
    {
        int n4x = TOK * DIM_ / 4, n4q = N_QKV * DIM_ / 4, n4p = DIM_ * DIM_ / 4;
        to_fp16<<<(n4x + 255) / 256, 256>>>((const float4*)x, xh, n4x);
        to_fp16<<<(n4q + 255) / 256, 256>>>((const float4*)Wqkv, wqh, n4q);
        to_fp16<<<(n4p + 255) / 256, 256>>>((const float4*)Wproj, wph, n4p);
    }

    // 1) QKV GEMM (fp16) + fused bias/RMSNorm/RoPE -> g_qh, g_kh, g_vh
    {
        dim3 grid(N_QKV / 128, TOK / 128);
        gemm_h<1><<<grid, 256, GEMM_SMEM>>>(xh, wqh, bqkv, nullptr,
                                            pe, q_scale, k_scale,
                                            TOK, N_QKV, DIM_);
    }
    // 2) flash attention (fp16 m16n8k16, cp.async)
    {
        dim3 grid(L_ / 128, H_, B_);
        attn_h<<<grid, 256, ATTN_SMEM>>>();
    }
    // 3) output projection (fp16)
    {
        dim3 grid(DIM_ / 128, TOK / 128);
        gemm_h<0><<<grid, 256, GEMM_SMEM>>>(oh, wph, bproj, out,
                                            nullptr, nullptr, nullptr,
                                            TOK, DIM_, DIM_);
    }
}